// round 3
// baseline (speedup 1.0000x reference)
#include <cuda_runtime.h>
#include <math.h>

#define BB  128   // batch
#define TT  256   // time steps
#define TD  256   // feature dim D
#define NS  32    // stack depth

// Scratch for precomputed latch gates g[b][t] (allocation-free rule: __device__ global)
__device__ float g_scratch[BB * TT];

// ---------------------------------------------------------------------------
// Kernel 1: precompute g[b][t] = elu(cos_sim(latch_enable, x[b,t,:]))
// One warp per (b,t). 8 warps / block. Memory-bound single pass over x.
// ---------------------------------------------------------------------------
__global__ void __launch_bounds__(256) precompute_g_kernel(
    const float* __restrict__ x,
    const float* __restrict__ le)
{
    const int warp = threadIdx.x >> 5;
    const int lane = threadIdx.x & 31;
    const int bt   = blockIdx.x * 8 + warp;
    const float* xp = x + (size_t)bt * TD;

    float dot = 0.f, nx = 0.f, nl = 0.f;
#pragma unroll
    for (int k = 0; k < 8; k++) {
        float xv = xp[lane + k * 32];
        float lv = le[lane + k * 32];
        dot = fmaf(lv, xv, dot);
        nx  = fmaf(xv, xv, nx);
        nl  = fmaf(lv, lv, nl);
    }
#pragma unroll
    for (int o = 16; o; o >>= 1) {
        dot += __shfl_xor_sync(0xffffffffu, dot, o);
        nx  += __shfl_xor_sync(0xffffffffu, nx,  o);
        nl  += __shfl_xor_sync(0xffffffffu, nl,  o);
    }
    if (lane == 0) {
        float an = fmaxf(sqrtf(nl), 1e-8f);
        float bn = fmaxf(sqrtf(nx), 1e-8f);
        float c  = dot / (an * bn);
        float g  = (c > 0.f) ? c : expm1f(c);
        g_scratch[bt] = g;
    }
}

// ---------------------------------------------------------------------------
// Kernel 2: the sequential scan. One CTA per batch element, thread d owns
// stack column d (32 regs). Pointer state lives in warp 0's lanes.
// One __syncthreads per step; double-buffered shared staging.
// ---------------------------------------------------------------------------
__global__ void __launch_bounds__(TD) stack_scan_kernel(
    const float* __restrict__ x,
    const float* __restrict__ should_pop,
    const float* __restrict__ sharpen_ptr,
    const float* __restrict__ latch_init,
    float* __restrict__ out)
{
    __shared__ float4 coef[2][NS];     // {a, b, c, p_sharpened} per stack slot
    __shared__ float2 partial[2][8];   // per-warp (sp.latch, |latch|^2)
    __shared__ float  initred[8][3];

    const int b    = blockIdx.x;
    const int d    = threadIdx.x;
    const int warp = d >> 5;
    const int lane = d & 31;

    const float sp      = should_pop[d];
    float       latch   = latch_init[b * TD + d];
    const float sharpen = sharpen_ptr[0];

    float st[NS];
#pragma unroll
    for (int n = 0; n < NS; n++) st[n] = 1e-6f;

    // pointer state: lane n of warp 0 holds ptr[n]
    float ptr = (warp == 0) ? ((lane == 0) ? 1.0f : 1e-6f) : 0.f;

    // ---- initial reduction: sp.latch, |latch|^2, |sp|^2 ----
    {
        float r0 = sp * latch, r1 = latch * latch, r2 = sp * sp;
#pragma unroll
        for (int o = 16; o; o >>= 1) {
            r0 += __shfl_xor_sync(0xffffffffu, r0, o);
            r1 += __shfl_xor_sync(0xffffffffu, r1, o);
            r2 += __shfl_xor_sync(0xffffffffu, r2, o);
        }
        if (lane == 0) { initred[warp][0] = r0; initred[warp][1] = r1; initred[warp][2] = r2; }
    }
    __syncthreads();

    float dotA = 0.f, nl2 = 0.f, sp2 = 0.f;
#pragma unroll
    for (int w = 0; w < 8; w++) {
        dotA += initred[w][0]; nl2 += initred[w][1]; sp2 += initred[w][2];
    }
    const float an = fmaxf(sqrtf(sp2), 1e-8f);

    const float* xb = x + (size_t)b * TT * TD;
    float*       ob = out + (size_t)b * TT * TD;
    const float* gb = g_scratch + b * TT;

    for (int t = 0; t < TT; t++) {
        // issue input load early
        const float inp = xb[t * TD + d];
        const float g   = gb[t];

        // pop gate from PREVIOUS latch state (all threads compute redundantly)
        float bn   = fmaxf(sqrtf(nl2), 1e-8f);
        float cosv = dotA / (an * bn);
        float pop  = (cosv > 0.f) ? cosv : expm1f(cosv);
        float push = 1.0f - pop;
        const int buf = t & 1;

        // ---- warp 0: pointer machinery (uses OLD ptr, produces coefs + new p) ----
        if (warp == 0) {
            float p_push = __shfl_sync(0xffffffffu, ptr, (lane + 31) & 31);  // roll +1
            float p_pop  = __shfl_sync(0xffffffffu, ptr, (lane + 1) & 31);   // roll -1
            float e = push * p_push;          // b coef
            float f = pop * ptr;
            float a = 1.0f - e - f;           // a coef
            float np = fmaf(pop, p_pop, e);   // new_ptr (pre-sharpen)
            float q  = powf(fmaxf(fmaxf(np, 0.f), 1e-12f), sharpen);
            float ssum = q;
#pragma unroll
            for (int o = 16; o; o >>= 1) ssum += __shfl_xor_sync(0xffffffffu, ssum, o);
            float pnew = q / fmaxf(ssum, 1e-8f);
            coef[buf][lane] = make_float4(a, e, 1e-6f * f, pnew);
            ptr = pnew;                        // carried pointer = sharpened p
        }

        // ---- all threads: latch update + 2-value block reduction ----
        latch = fmaf(g, inp, (1.0f - g) * latch);
        float q0 = sp * latch, q1 = latch * latch;
#pragma unroll
        for (int o = 16; o; o >>= 1) {
            q0 += __shfl_xor_sync(0xffffffffu, q0, o);
            q1 += __shfl_xor_sync(0xffffffffu, q1, o);
        }
        if (lane == 0) partial[buf][warp] = make_float2(q0, q1);

        __syncthreads();

        // finish reduction locally (broadcast reads, no second barrier)
        dotA = 0.f; nl2 = 0.f;
#pragma unroll
        for (int w = 0; w < 8; w++) {
            float2 pw = partial[buf][w];
            dotA += pw.x; nl2 += pw.y;
        }

        // ---- stack update + readout ----
        float s = 0.f;
#pragma unroll
        for (int n = 0; n < NS; n++) {
            float4 cf = coef[buf][n];
            float v = fmaf(cf.x, st[n], fmaf(cf.y, inp, cf.z));
            st[n] = v;
            s = fmaf(v, cf.w, s);
        }
        ob[t * TD + d] = pop * s;
    }
}

// ---------------------------------------------------------------------------
// metadata order: x[B*T*D], should_pop[D], sharpen_pointer[1],
//                 latch_enable[D], latch_init[B*D]  -> out[B*T*D] float32
// ---------------------------------------------------------------------------
extern "C" void kernel_launch(void* const* d_in, const int* in_sizes, int n_in,
                              void* d_out, int out_size)
{
    const float* x   = (const float*)d_in[0];
    const float* sp  = (const float*)d_in[1];
    const float* shp = (const float*)d_in[2];
    const float* le  = (const float*)d_in[3];
    const float* li  = (const float*)d_in[4];
    float* out = (float*)d_out;

    precompute_g_kernel<<<(BB * TT) / 8, 256>>>(x, le);
    stack_scan_kernel<<<BB, TD>>>(x, sp, shp, li, out);
}